// round 7
// baseline (speedup 1.0000x reference)
#include <cuda_runtime.h>
#include <cstdint>
#include <cmath>

// ---------------------------------------------------------------------------
// SpecAugment: out = where(freq_mask[b,f] | time_mask[b,t], 0, x)
// Host computes the 1280 threefry draws (bit-exact, verified rel_err=0.0),
// passed as __grid_constant__. Device: SINGLE-WAVE PERSISTENT layout —
// grid = 128 batches x 5 blocks, every block resident at once (no wave
// transitions). Each block owns one batch b, builds the time mask + nibbles
// ONCE, then streams 16 rows (f = k, k+5, ..., 75): 4 front-batched float4
// loads (skipped where masked) + 4 streaming stores per row.
// ---------------------------------------------------------------------------

#define B_DIM 128
#define F_DIM 80
#define T_DIM 4000
#define T4    1000          // float4 per row
#define TW    125           // 32-bit time-mask words per batch
#define NTHREADS 256
#define BLKS_PER_B 5
#define ROWS_PER_BLK (F_DIM / BLKS_PER_B)     // 16

struct MaskParams {
    uint32_t frow[(B_DIM * F_DIM + 31) / 32];  // bit per (b,f) row
    short ts[B_DIM * 10];                      // time band start
    short te[B_DIM * 10];                      // time band end (exclusive)
};

// ============================ device ======================================

__global__ void __launch_bounds__(NTHREADS, BLKS_PER_B)
apply_kernel(const float4* __restrict__ x, float4* __restrict__ out,
             const __grid_constant__ MaskParams p)
{
    const int b   = blockIdx.x / BLKS_PER_B;   // fixed batch for this block
    const int k   = blockIdx.x % BLKS_PER_B;   // f stride phase
    const int tid = threadIdx.x;

    // Build this batch's packed time mask in shared (125 words, 10 bands). Once.
    __shared__ uint32_t s_tb[TW];
    if (tid < TW) {
        const int base = tid * 32;
        uint32_t word = 0u;
#pragma unroll
        for (int m = 0; m < 10; m++) {
            int s = p.ts[b * 10 + m], e = p.te[b * 10 + m];
            int lo = s - base;  lo = lo < 0  ? 0  : lo;
            int hi = e - base;  hi = hi > 32 ? 32 : hi;
            if (hi > lo) {
                uint32_t mhi = (hi >= 32) ? 0xFFFFFFFFu : ((1u << hi) - 1u);
                word |= mhi & ~((1u << lo) - 1u);
            }
        }
        s_tb[tid] = word;
    }
    __syncthreads();

    // Per-t4 nibbles: computed once, reused for all 16 rows (same batch).
    uint32_t nib[4];
    bool     live[4];   // t4 in range AND not fully time-masked
#pragma unroll
    for (int i = 0; i < 4; i++) {
        int t4 = tid + i * NTHREADS;
        nib[i]  = (t4 < T4) ? ((s_tb[t4 >> 3] >> ((t4 & 7) * 4)) & 0xFu) : 0xFu;
        live[i] = (t4 < T4) && (nib[i] != 0xFu);
    }

    const float4 z = make_float4(0.f, 0.f, 0.f, 0.f);

    for (int j = 0; j < ROWS_PER_BLK; j++) {
        const int f   = k + j * BLKS_PER_B;
        const int row = b * F_DIM + f;
        const bool fm = (p.frow[row >> 5] >> (row & 31)) & 1u;

        const float4* xr   = x   + (size_t)row * T4;
        float4*       orow = out + (size_t)row * T4;

        if (fm) {
            // Entire row frequency-masked: store zeros, read nothing.
#pragma unroll
            for (int i = 0; i < 4; i++) {
                int t4 = tid + i * NTHREADS;
                if (t4 < T4) __stcs(orow + t4, z);
            }
            continue;
        }

        float4 v[4];
        // Front-batched streaming loads; fully-masked float4s skipped.
#pragma unroll
        for (int i = 0; i < 4; i++) {
            int t4 = tid + i * NTHREADS;
            v[i] = z;
            if (live[i]) v[i] = __ldcs(xr + t4);
        }
#pragma unroll
        for (int i = 0; i < 4; i++) {
            int t4 = tid + i * NTHREADS;
            if (t4 >= T4) continue;
            float4 o = v[i];
            o.x = (nib[i] & 1u) ? 0.f : o.x;
            o.y = (nib[i] & 2u) ? 0.f : o.y;
            o.z = (nib[i] & 4u) ? 0.f : o.z;
            o.w = (nib[i] & 8u) ? 0.f : o.w;
            __stcs(orow + t4, o);
        }
    }
}

// ============================ host: threefry draws ========================

namespace sa_host {

struct U2 { uint32_t a, b; };

static inline U2 tf(uint32_t k0, uint32_t k1, uint32_t x0, uint32_t x1) {
    const uint32_t ks2 = k0 ^ k1 ^ 0x1BD11BDAu;
    x0 += k0; x1 += k1;
#define RND(r) { x0 += x1; x1 = (x1 << (r)) | (x1 >> (32 - (r))); x1 ^= x0; }
    RND(13) RND(15) RND(26) RND(6)
    x0 += k1;  x1 += ks2 + 1u;
    RND(17) RND(29) RND(16) RND(24)
    x0 += ks2; x1 += k0 + 2u;
    RND(13) RND(15) RND(26) RND(6)
    x0 += k0;  x1 += k1 + 3u;
    RND(17) RND(29) RND(16) RND(24)
    x0 += k1;  x1 += ks2 + 4u;
    RND(13) RND(15) RND(26) RND(6)
    x0 += ks2; x1 += k0 + 5u;
#undef RND
    return U2{x0, x1};
}

// jax_threefry_partitionable = True (verified bit-exact)
static inline U2 split_a(U2 k) { return tf(k.a, k.b, 0u, 0u); }
static inline U2 split_b(U2 k) { return tf(k.a, k.b, 0u, 1u); }
static inline uint32_t rbits(U2 k, uint32_t j) {
    U2 o = tf(k.a, k.b, 0u, j);
    return o.a ^ o.b;
}

static void fill_params(MaskParams& p) {
    U2 key{0u, 42u};                       // jax.random.key(42)
    U2 kf  = split_a(key), kt  = split_b(key);
    U2 kwf = split_a(kf),  ksf = split_b(kf);
    U2 kwt = split_a(kt),  kst = split_b(kt);
    U2 k1f = split_a(kwf), k2f = split_b(kwf);
    U2 k1t = split_a(kwt), k2t = split_b(kwt);

    // Freq: (128, 2) draws, span 28, multiplier 2^32 % 28 = 4
    int fs[B_DIM * 2], fe[B_DIM * 2];
    for (int j = 0; j < B_DIM * 2; j++) {
        uint32_t h  = rbits(k1f, (uint32_t)j);
        uint32_t l  = rbits(k2f, (uint32_t)j);
        uint32_t ub = rbits(ksf, (uint32_t)j);
        uint32_t w  = ((h % 28u) * 4u + (l % 28u)) % 28u;
        float u  = (float)(ub >> 9) * (1.0f / 8388608.0f);  // exact [0,1)
        int hi   = F_DIM - (int)w;                          // max(1,80-w), w<=27
        int s    = (int)(u * (float)hi);
        fs[j] = s; fe[j] = s + (int)w;
    }
    for (int i = 0; i < (int)(sizeof(p.frow) / sizeof(p.frow[0])); i++) p.frow[i] = 0u;
    for (int b = 0; b < B_DIM; b++)
        for (int f = 0; f < F_DIM; f++) {
            bool in = (f >= fs[2 * b]     && f < fe[2 * b]) ||
                      (f >= fs[2 * b + 1] && f < fe[2 * b + 1]);
            if (in) {
                int r = b * F_DIM + f;
                p.frow[r >> 5] |= 1u << (r & 31);
            }
        }

    // Time: (128, 10) draws, span 101, multiplier 2^32 % 101 = 68
    for (int j = 0; j < B_DIM * 10; j++) {
        uint32_t h  = rbits(k1t, (uint32_t)j);
        uint32_t l  = rbits(k2t, (uint32_t)j);
        uint32_t ub = rbits(kst, (uint32_t)j);
        uint32_t w  = ((h % 101u) * 68u + (l % 101u)) % 101u;
        float u  = (float)(ub >> 9) * (1.0f / 8388608.0f);
        int hi   = T_DIM - (int)w;                          // max(1,4000-w), w<=100
        int s    = (int)(u * (float)hi);
        p.ts[j] = (short)s;
        p.te[j] = (short)(s + (int)w);
    }
}

} // namespace sa_host

// ============================ launch ======================================

extern "C" void kernel_launch(void* const* d_in, const int* in_sizes, int n_in,
                              void* d_out, int out_size) {
    (void)in_sizes; (void)n_in; (void)out_size;
    const float4* x   = (const float4*)d_in[0];
    float4*       out = (float4*)d_out;

    MaskParams p;
    sa_host::fill_params(p);

    apply_kernel<<<B_DIM * BLKS_PER_B, NTHREADS>>>(x, out, p);
}

// round 8
// speedup vs baseline: 1.1899x; 1.1899x over previous
#include <cuda_runtime.h>
#include <cstdint>
#include <cmath>

// ---------------------------------------------------------------------------
// SpecAugment: out = where(freq_mask[b,f] | time_mask[b,t], 0, x)
// Host computes the 1280 threefry draws (bit-exact, verified rel_err=0.0),
// passed as __grid_constant__. Device: ONE ROW PER 128-THREAD BLOCK
// (fine-grained => HW work-steal balances masked/unmasked rows), with all
// 8 float4 loads front-batched per thread (MLP_p1=8), masked loads skipped.
// ---------------------------------------------------------------------------

#define B_DIM 128
#define F_DIM 80
#define T_DIM 4000
#define T4    1000          // float4 per row
#define TW    125           // 32-bit time-mask words per batch
#define NTHREADS 128
#define VEC 8               // float4 per thread (128 * 8 = 1024 >= 1000)

struct MaskParams {
    uint32_t frow[(B_DIM * F_DIM + 31) / 32];  // bit per (b,f) row
    short ts[B_DIM * 10];                      // time band start
    short te[B_DIM * 10];                      // time band end (exclusive)
};

// ============================ device ======================================

__global__ void __launch_bounds__(NTHREADS)
apply_kernel(const float4* __restrict__ x, float4* __restrict__ out,
             const __grid_constant__ MaskParams p)
{
    const int row = blockIdx.x;                // row = b*80 + f (contiguous)
    const int b   = row / F_DIM;
    const int tid = threadIdx.x;

    const float4* xr   = x   + (size_t)row * T4;
    float4*       orow = out + (size_t)row * T4;
    const float4  z    = make_float4(0.f, 0.f, 0.f, 0.f);

    // Freq-masked row: store zeros, read nothing, exit fast (work-steal
    // backfills this SM slot with another block).
    if ((p.frow[row >> 5] >> (row & 31)) & 1u) {
#pragma unroll
        for (int i = 0; i < VEC; i++) {
            int t4 = tid + i * NTHREADS;
            if (t4 < T4) __stcs(orow + t4, z);
        }
        return;
    }

    // Build this batch's packed time mask in shared (125 words, 10 bands).
    __shared__ uint32_t s_tb[TW];
    if (tid < TW) {
        const int base = tid * 32;
        uint32_t word = 0u;
#pragma unroll
        for (int m = 0; m < 10; m++) {
            int s = p.ts[b * 10 + m], e = p.te[b * 10 + m];
            int lo = s - base;  lo = lo < 0  ? 0  : lo;
            int hi = e - base;  hi = hi > 32 ? 32 : hi;
            if (hi > lo) {
                uint32_t mhi = (hi >= 32) ? 0xFFFFFFFFu : ((1u << hi) - 1u);
                word |= mhi & ~((1u << lo) - 1u);
            }
        }
        s_tb[tid] = word;
    }
    __syncthreads();

    // Per-t4 nibbles.
    uint32_t nib[VEC];
#pragma unroll
    for (int i = 0; i < VEC; i++) {
        int t4 = tid + i * NTHREADS;
        nib[i] = (t4 < T4) ? ((s_tb[t4 >> 3] >> ((t4 & 7) * 4)) & 0xFu) : 0xFu;
    }

    // ALL loads front-batched (up to 8 outstanding); fully-masked skipped.
    float4 v[VEC];
#pragma unroll
    for (int i = 0; i < VEC; i++) {
        int t4 = tid + i * NTHREADS;
        v[i] = z;
        if (t4 < T4 && nib[i] != 0xFu) v[i] = __ldcs(xr + t4);
    }

    // Streaming stores.
#pragma unroll
    for (int i = 0; i < VEC; i++) {
        int t4 = tid + i * NTHREADS;
        if (t4 >= T4) continue;
        float4 o = v[i];
        o.x = (nib[i] & 1u) ? 0.f : o.x;
        o.y = (nib[i] & 2u) ? 0.f : o.y;
        o.z = (nib[i] & 4u) ? 0.f : o.z;
        o.w = (nib[i] & 8u) ? 0.f : o.w;
        __stcs(orow + t4, o);
    }
}

// ============================ host: threefry draws ========================

namespace sa_host {

struct U2 { uint32_t a, b; };

static inline U2 tf(uint32_t k0, uint32_t k1, uint32_t x0, uint32_t x1) {
    const uint32_t ks2 = k0 ^ k1 ^ 0x1BD11BDAu;
    x0 += k0; x1 += k1;
#define RND(r) { x0 += x1; x1 = (x1 << (r)) | (x1 >> (32 - (r))); x1 ^= x0; }
    RND(13) RND(15) RND(26) RND(6)
    x0 += k1;  x1 += ks2 + 1u;
    RND(17) RND(29) RND(16) RND(24)
    x0 += ks2; x1 += k0 + 2u;
    RND(13) RND(15) RND(26) RND(6)
    x0 += k0;  x1 += k1 + 3u;
    RND(17) RND(29) RND(16) RND(24)
    x0 += k1;  x1 += ks2 + 4u;
    RND(13) RND(15) RND(26) RND(6)
    x0 += ks2; x1 += k0 + 5u;
#undef RND
    return U2{x0, x1};
}

// jax_threefry_partitionable = True (verified bit-exact)
static inline U2 split_a(U2 k) { return tf(k.a, k.b, 0u, 0u); }
static inline U2 split_b(U2 k) { return tf(k.a, k.b, 0u, 1u); }
static inline uint32_t rbits(U2 k, uint32_t j) {
    U2 o = tf(k.a, k.b, 0u, j);
    return o.a ^ o.b;
}

static void fill_params(MaskParams& p) {
    U2 key{0u, 42u};                       // jax.random.key(42)
    U2 kf  = split_a(key), kt  = split_b(key);
    U2 kwf = split_a(kf),  ksf = split_b(kf);
    U2 kwt = split_a(kt),  kst = split_b(kt);
    U2 k1f = split_a(kwf), k2f = split_b(kwf);
    U2 k1t = split_a(kwt), k2t = split_b(kwt);

    // Freq: (128, 2) draws, span 28, multiplier 2^32 % 28 = 4
    int fs[B_DIM * 2], fe[B_DIM * 2];
    for (int j = 0; j < B_DIM * 2; j++) {
        uint32_t h  = rbits(k1f, (uint32_t)j);
        uint32_t l  = rbits(k2f, (uint32_t)j);
        uint32_t ub = rbits(ksf, (uint32_t)j);
        uint32_t w  = ((h % 28u) * 4u + (l % 28u)) % 28u;
        float u  = (float)(ub >> 9) * (1.0f / 8388608.0f);  // exact [0,1)
        int hi   = F_DIM - (int)w;                          // max(1,80-w), w<=27
        int s    = (int)(u * (float)hi);
        fs[j] = s; fe[j] = s + (int)w;
    }
    for (int i = 0; i < (int)(sizeof(p.frow) / sizeof(p.frow[0])); i++) p.frow[i] = 0u;
    for (int b = 0; b < B_DIM; b++)
        for (int f = 0; f < F_DIM; f++) {
            bool in = (f >= fs[2 * b]     && f < fe[2 * b]) ||
                      (f >= fs[2 * b + 1] && f < fe[2 * b + 1]);
            if (in) {
                int r = b * F_DIM + f;
                p.frow[r >> 5] |= 1u << (r & 31);
            }
        }

    // Time: (128, 10) draws, span 101, multiplier 2^32 % 101 = 68
    for (int j = 0; j < B_DIM * 10; j++) {
        uint32_t h  = rbits(k1t, (uint32_t)j);
        uint32_t l  = rbits(k2t, (uint32_t)j);
        uint32_t ub = rbits(kst, (uint32_t)j);
        uint32_t w  = ((h % 101u) * 68u + (l % 101u)) % 101u;
        float u  = (float)(ub >> 9) * (1.0f / 8388608.0f);
        int hi   = T_DIM - (int)w;                          // max(1,4000-w), w<=100
        int s    = (int)(u * (float)hi);
        p.ts[j] = (short)s;
        p.te[j] = (short)(s + (int)w);
    }
}

} // namespace sa_host

// ============================ launch ======================================

extern "C" void kernel_launch(void* const* d_in, const int* in_sizes, int n_in,
                              void* d_out, int out_size) {
    (void)in_sizes; (void)n_in; (void)out_size;
    const float4* x   = (const float4*)d_in[0];
    float4*       out = (float4*)d_out;

    MaskParams p;
    sa_host::fill_params(p);

    apply_kernel<<<B_DIM * F_DIM, NTHREADS>>>(x, out, p);
}